// round 3
// baseline (speedup 1.0000x reference)
#include <cuda_runtime.h>

#define Bv 8
#define Tv 1000
#define Dv 1024

// Scratch (__device__ globals per allocation rules)
__device__ float g_part[8 * 8 * 1024];    // 8 chunks x 8 batches x 1024 cols
__device__ float g_vsum[8 * 64];          // sum_t v[b,:]
__device__ float g_wosum[64 * 1024];      // sum_h Wo[h*64+d, n]
__device__ float g_row[8 * 1024];         // per-batch output row

// ---------------------------------------------------------------------------
// 1) Partial sums over t: 8 chunks of 125 timesteps, per batch.
//    grid (8, 8), 256 threads, one float4 column-slice per thread.
// ---------------------------------------------------------------------------
__global__ void __launch_bounds__(256)
xsum_part_kernel(const float* __restrict__ x)
{
    const int chunk = blockIdx.x;       // 0..7
    const int b     = blockIdx.y;       // 0..7
    const int j4    = threadIdx.x << 2; // 0..1020

    const float4* xp = (const float4*)(x + ((size_t)b * Tv + chunk * 125) * Dv + j4);
    float4 acc = make_float4(0.f, 0.f, 0.f, 0.f);
    #pragma unroll 5
    for (int tt = 0; tt < 125; tt++) {
        float4 v = xp[(size_t)tt * (Dv / 4)];
        acc.x += v.x; acc.y += v.y; acc.z += v.z; acc.w += v.w;
    }
    *(float4*)(g_part + ((size_t)(chunk * 8 + b)) * Dv + j4) = acc;
}

// ---------------------------------------------------------------------------
// 2) Fused: reduce 8 partials -> xsum (smem), then Vsum[b,d] = xsum @ Wv + T*bv.
//    grid 8 (per batch), 256 threads.
// ---------------------------------------------------------------------------
__global__ void __launch_bounds__(256)
vsum_fused_kernel(const float* __restrict__ Wv, const float* __restrict__ bv)
{
    __shared__ __align__(16) float xs[1024];
    __shared__ float part[4][64];
    const int b = blockIdx.x;

    // Phase 1: reduce partials for this batch (thread owns one float4 slice)
    {
        const int j4 = threadIdx.x << 2;
        float4 acc = make_float4(0.f, 0.f, 0.f, 0.f);
        #pragma unroll
        for (int c = 0; c < 8; c++) {
            float4 v = *(const float4*)(g_part + ((size_t)(c * 8 + b)) * Dv + j4);
            acc.x += v.x; acc.y += v.y; acc.z += v.z; acc.w += v.w;
        }
        *(float4*)(xs + j4) = acc;
    }
    __syncthreads();

    // Phase 2: Vsum[b,d] = sum_j xs[j] * Wv[j,d]
    const int d   = threadIdx.x & 63;
    const int seg = threadIdx.x >> 6;   // 0..3
    float s = 0.f;
    #pragma unroll 8
    for (int jj = 0; jj < 256; jj++) {
        int j = seg * 256 + jj;
        s += xs[j] * Wv[(size_t)j * 64 + d];
    }
    part[seg][d] = s;
    __syncthreads();
    if (seg == 0)
        g_vsum[b * 64 + d] = part[0][d] + part[1][d] + part[2][d] + part[3][d]
                             + (float)Tv * bv[d];
}

// ---------------------------------------------------------------------------
// 3) WoSum[d,n] = sum_h Wo[h*64+d, n]. Flattened float4 grid:
//    16384 float4 outputs, grid 64 x 256 threads, 16 x LDG.128 per thread.
// ---------------------------------------------------------------------------
__global__ void __launch_bounds__(256)
wosum_kernel(const float* __restrict__ Wo)
{
    const int f4 = blockIdx.x * 256 + threadIdx.x;  // 0..16383
    const int d  = f4 >> 8;                         // 0..63
    const int n4 = (f4 & 255) << 2;                 // 0..1020

    float4 acc = make_float4(0.f, 0.f, 0.f, 0.f);
    #pragma unroll
    for (int h = 0; h < 16; h++) {
        float4 v = *(const float4*)(Wo + ((size_t)(h * 64 + d)) * Dv + n4);
        acc.x += v.x; acc.y += v.y; acc.z += v.z; acc.w += v.w;
    }
    *(float4*)(g_wosum + (size_t)d * Dv + n4) = acc;
}

// ---------------------------------------------------------------------------
// 4) row[b,n] = bo[n] + sum_d Vsum[b,d] * WoSum[d,n]. grid 8, 256 threads,
//    one float4 per thread.
// ---------------------------------------------------------------------------
__global__ void __launch_bounds__(256)
row_kernel(const float* __restrict__ bo)
{
    const int b  = blockIdx.x;
    const int n4 = threadIdx.x << 2;

    float4 acc = *(const float4*)(bo + n4);
    #pragma unroll
    for (int d = 0; d < 64; d++) {
        float vs = g_vsum[b * 64 + d];
        float4 w = *(const float4*)(g_wosum + (size_t)d * Dv + n4);
        acc.x += vs * w.x; acc.y += vs * w.y;
        acc.z += vs * w.z; acc.w += vs * w.w;
    }
    *(float4*)(g_row + b * Dv + n4) = acc;
}

// ---------------------------------------------------------------------------
// 5) Broadcast: one block per output row (b*1000+t), 256 threads x float4.
// ---------------------------------------------------------------------------
__global__ void __launch_bounds__(256)
bcast_kernel(float* __restrict__ out)
{
    const int row = blockIdx.x;          // 0..7999
    const int b   = row / Tv;
    float4 v = ((const float4*)g_row)[b * 256 + threadIdx.x];
    ((float4*)out)[(size_t)row * 256 + threadIdx.x] = v;
}

// ---------------------------------------------------------------------------
extern "C" void kernel_launch(void* const* d_in, const int* in_sizes, int n_in,
                              void* d_out, int out_size)
{
    const float* x  = (const float*)d_in[0];
    const float* Wv = (const float*)d_in[5];
    const float* bv = (const float*)d_in[6];
    const float* Wo = (const float*)d_in[7];
    const float* bo = (const float*)d_in[8];
    float* out = (float*)d_out;

    xsum_part_kernel<<<dim3(8, 8), 256>>>(x);
    vsum_fused_kernel<<<8, 256>>>(Wv, bv);
    wosum_kernel<<<64, 256>>>(Wo);
    row_kernel<<<8, 256>>>(bo);
    bcast_kernel<<<Bv * Tv, 256>>>(out);
}

// round 4
// speedup vs baseline: 1.7538x; 1.7538x over previous
#include <cuda_runtime.h>

#define Bv 8
#define Tv 1000
#define Dv 1024

// Scratch (__device__ globals per allocation rules)
__device__ float g_part[25 * 8 * 1024];   // 25 t-chunks x 8 batches x 1024 cols
__device__ float g_vsump[4 * 8 * 64];     // 4 j-block partials of vsum

// ---------------------------------------------------------------------------
// 1) Partial sums over t: 25 chunks of 40 timesteps, per batch.
//    grid (25, 8), 256 threads, one float4 column-slice per thread.
// ---------------------------------------------------------------------------
__global__ void __launch_bounds__(256)
xsum_part_kernel(const float* __restrict__ x)
{
    const int chunk = blockIdx.x;       // 0..24
    const int b     = blockIdx.y;       // 0..7
    const int j4    = threadIdx.x << 2; // 0..1020

    const float4* xp = (const float4*)(x + ((size_t)b * Tv + chunk * 40) * Dv + j4);
    float4 acc = make_float4(0.f, 0.f, 0.f, 0.f);
    #pragma unroll 10
    for (int tt = 0; tt < 40; tt++) {
        float4 v = xp[(size_t)tt * (Dv / 4)];
        acc.x += v.x; acc.y += v.y; acc.z += v.z; acc.w += v.w;
    }
    *(float4*)(g_part + ((size_t)(chunk * 8 + b)) * Dv + j4) = acc;
}

// ---------------------------------------------------------------------------
// 2) vsum partials: grid (8 b, 4 jblk). Each block reduces its 256-j slice of
//    the 25 x-partials, then GEMVs that slice against Wv -> g_vsump[jblk][b][64].
// ---------------------------------------------------------------------------
__global__ void __launch_bounds__(256)
vsum_part_kernel(const float* __restrict__ Wv)
{
    __shared__ float xs[256];
    __shared__ float p[4][64];
    const int b    = blockIdx.x;
    const int jblk = blockIdx.y;
    const int tid  = threadIdx.x;
    const int jg   = jblk * 256;

    // Reduce 25 chunk-partials for this 256-wide j slice
    {
        float s = 0.f;
        #pragma unroll
        for (int c = 0; c < 25; c++)
            s += g_part[((size_t)(c * 8 + b)) * Dv + jg + tid];
        xs[tid] = s;
    }
    __syncthreads();

    // GEMV: each of 4 sub-segments handles 64 j's for all 64 d's
    const int d   = tid & 63;
    const int sub = tid >> 6;
    float acc = 0.f;
    #pragma unroll 16
    for (int jj = 0; jj < 64; jj++) {
        int j = sub * 64 + jj;
        acc += xs[j] * Wv[(size_t)(jg + j) * 64 + d];
    }
    p[sub][d] = acc;
    __syncthreads();
    if (tid < 64)
        g_vsump[(jblk * 8 + b) * 64 + tid] =
            p[0][tid] + p[1][tid] + p[2][tid] + p[3][tid];
}

// ---------------------------------------------------------------------------
// 3) Fused row-GEMV + broadcast write.
//    grid (32 n-blocks, 4 t-chunks), 256 threads.
//    row[b,n] = bo[n] + sum_m vs[b, m&63] * Wo[m, n]
//    Warp w handles m in [w*128, w*128+128): the two 64-aligned halves share
//    d = m&63, so fold (w1+w2) before the 8 batch-FMAs.
//    Then the block streams out[b, t0..t0+249, n0..n0+31] for all 8 batches.
// ---------------------------------------------------------------------------
__global__ void __launch_bounds__(256)
row_bcast_kernel(const float* __restrict__ Wo, const float* __restrict__ bv,
                 const float* __restrict__ bo, float* __restrict__ out)
{
    __shared__ float vs[8 * 64];      // vsum[b][d]
    __shared__ float part[8][8][32];  // [warp][b][lane]
    __shared__ float fin[8][32];      // final row slice [b][lane]

    const int n0   = blockIdx.x * 32;
    const int t0   = blockIdx.y * 250;
    const int tid  = threadIdx.x;
    const int lane = tid & 31;
    const int wid  = tid >> 5;
    const int n    = n0 + lane;

    // Assemble vsum: 4 j-block partials + T*bv. 512 values, 2 per thread.
    #pragma unroll
    for (int i = tid; i < 512; i += 256) {
        int d = i & 63;
        float s = (float)Tv * bv[d];
        #pragma unroll
        for (int jb = 0; jb < 4; jb++)
            s += g_vsump[jb * 512 + i];
        vs[i] = s;
    }
    __syncthreads();

    // GEMV over this warp's 128 m-rows
    float acc[8] = {};
    const int mbase = wid * 128;
    #pragma unroll 8
    for (int mm = 0; mm < 64; mm++) {
        float w1 = Wo[(size_t)(mbase + mm) * Dv + n];
        float w2 = Wo[(size_t)(mbase + mm + 64) * Dv + n];
        float w  = w1 + w2;
        #pragma unroll
        for (int b = 0; b < 8; b++)
            acc[b] = fmaf(vs[b * 64 + mm], w, acc[b]);
    }
    #pragma unroll
    for (int b = 0; b < 8; b++)
        part[wid][b][lane] = acc[b];
    __syncthreads();

    // Cross-warp reduce + bias: thread (b = tid>>5, lane)
    {
        int b = wid;
        float s = bo[n];
        #pragma unroll
        for (int w = 0; w < 8; w++)
            s += part[w][b][lane];
        fin[b][lane] = s;
    }
    __syncthreads();

    // Broadcast write: 250 t x 8 b rows, warp-per-row, 128B coalesced stores
    for (int idx = wid; idx < 250 * 8; idx += 8) {
        int b = idx & 7;
        int t = t0 + (idx >> 3);
        out[((size_t)(b * Tv + t)) * Dv + n] = fin[b][lane];
    }
}

// ---------------------------------------------------------------------------
extern "C" void kernel_launch(void* const* d_in, const int* in_sizes, int n_in,
                              void* d_out, int out_size)
{
    const float* x  = (const float*)d_in[0];
    const float* Wv = (const float*)d_in[5];
    const float* bv = (const float*)d_in[6];
    const float* Wo = (const float*)d_in[7];
    const float* bo = (const float*)d_in[8];
    float* out = (float*)d_out;

    xsum_part_kernel<<<dim3(25, 8), 256>>>(x);
    vsum_part_kernel<<<dim3(8, 4), 256>>>(Wv);
    row_bcast_kernel<<<dim3(32, 4), 256>>>(Wo, bv, bo, out);
}